// round 12
// baseline (speedup 1.0000x reference)
#include <cuda_runtime.h>
#include <cuda_fp16.h>

#define VOCAB 30000
#define DIM   768
#define SEQL  512
#define HWORDS (VOCAB / 2)   // packed 16-bit counts, 2 per u32
#define ROWH2 (DIM / 2)      // 384 half2 per Wt row

// Scratch: transposed weights Wt[VOCAB][DIM] (fp16, 46 MB). Device global
// per the allocation rules (no cudaMalloc anywhere).
__device__ __half g_Wt[(size_t)VOCAB * DIM];

// ---------------------------------------------------------------------------
// Transpose W [DIM, VOCAB] (row-major fp32) -> g_Wt [VOCAB, DIM] (fp16).
// 256-vocab x 64-dim tiles, 512 threads. Loads: 128B wavefronts (LDG.32,
// consecutive vocab per warp). Smem: half2 dim-pairs, 33-word row stride
// (conflict-free). Stores: warp writes one vocab row's 64 dims as half2
// per lane -> full 128B STG wavefronts.
// ---------------------------------------------------------------------------
#define TP_VT 256
#define TP_DT 64

__global__ __launch_bounds__(512)
void transpose_kernel(const float* __restrict__ W) {
    __shared__ __half2 tile[TP_VT][TP_DT / 2 + 1];   // [256][33] half2 ≈ 33.8 KB

    const int t0 = blockIdx.x * TP_VT;   // vocab tile base
    const int d0 = blockIdx.y * TP_DT;   // dim tile base
    const int v  = threadIdx.x & 31;     // vocab lane 0..31
    const int p  = threadIdx.x >> 5;     // warp id 0..15 -> dim-pair stepper

    // Load: for each 32-vocab chunk c (8 chunks) and dim-pair i (32 pairs,
    // 2 per warp), read two fp32 and pack as half2 into the tile.
#pragma unroll
    for (int c = 0; c < 8; c++) {
        int t = t0 + c * 32 + v;
        bool tv = (t < VOCAB);
#pragma unroll
        for (int i = p; i < 32; i += 16) {
            if (tv) {
                float fa = W[(size_t)(d0 + 2 * i)     * VOCAB + t];
                float fb = W[(size_t)(d0 + 2 * i + 1) * VOCAB + t];
                tile[c * 32 + v][i] = __floats2half2_rn(fa, fb);
            }
        }
    }
    __syncthreads();

    // Store: warp w writes vocab rows r = w, w+16, ...; lane l writes
    // half2 (dims d0+2l, d0+2l+1) -> 32 consecutive 4B words = 128B.
    const int wl = threadIdx.x & 31;
    const int w  = threadIdx.x >> 5;
#pragma unroll
    for (int r = w; r < TP_VT; r += 16) {
        int t = t0 + r;
        if (t < VOCAB)
            ((__half2*)&g_Wt[(size_t)t * DIM + d0])[wl] = tile[r][wl];
    }
}

// ---------------------------------------------------------------------------
// Main kernel: one CTA per document row.  (exact R11 structure — the schedule
// that sustains the LTS bandwidth cap. DO NOT restructure phase 4.)
//  Phase 1: validity + doc_len (syncthreads_count)
//  Phase 2: packed 16-bit histogram in smem (tf counts)
//  Phase 3: dedup (atomicAnd fetch-and-clear) + BM25 score per unique token
//  Phase 4: token-parallel fp16 gather, fp32 accumulate, smem reduce
//  Phase 5: L2 normalize, write out
// ---------------------------------------------------------------------------
// smem layout (u32 words): hist[15000] | redbuf[768] | score[512] | tok[512] | warpsum[16]
#define SMEM_WORDS (HWORDS + DIM + SEQL + SEQL + 16)
#define SMEM_BYTES (SMEM_WORDS * 4)

__global__ __launch_bounds__(512, 3)
void bm25_kernel(const int* __restrict__ ids,
                 const int* __restrict__ mask,
                 float* __restrict__ out) {
    extern __shared__ unsigned int sm[];
    unsigned int* hist   = sm;                                // HWORDS
    float*        redbuf = (float*)(sm + HWORDS);             // DIM
    float*        score  = redbuf + DIM;                      // SEQL
    int*          tok    = (int*)(score + SEQL);              // SEQL
    float*        warpsum = (float*)(tok + SEQL);             // 16

    const int tid = threadIdx.x;
    const int b   = blockIdx.x;

    // ---- Phase 1: load token, validity ----
    int id = ids [(size_t)b * SEQL + tid];
    int mk = mask[(size_t)b * SEQL + tid];
    bool valid = (mk == 1) && (id > 100) && (id < VOCAB);
    int  t = valid ? id : 0;

    // zero histogram + reduction buffer (completes before the barrier below)
#pragma unroll
    for (int i = tid; i < HWORDS; i += 512) hist[i] = 0u;
    for (int i = tid; i < DIM;    i += 512) redbuf[i] = 0.0f;

    int doc_len = __syncthreads_count(valid);   // barrier + valid count

    // ---- Phase 2: histogram (tf with multiplicity) ----
    const unsigned sh = ((unsigned)t & 1u) << 4;
    if (valid) atomicAdd(&hist[t >> 1], 1u << sh);
    __syncthreads();

    // ---- Phase 3: dedup + score ----
    float length_norm = fmaxf(1.0f + 0.75f * ((float)doc_len * 0.01f - 1.0f), 0.5f);
    float s = 0.0f;
    if (valid) {
        unsigned old = atomicAnd(&hist[t >> 1], ~(0xFFFFu << sh));
        unsigned cnt = (old >> sh) & 0xFFFFu;
        if (cnt) {
            float tf = (float)cnt;
            s = tf * 2.2f / (tf + 1.2f * length_norm);   // (K1+1)=2.2, K1=1.2
        }
    }
    score[tid] = s;   // 0 for invalid tokens and duplicate occurrences
    tok[tid]   = t;   // 0 for invalid (loads Wt row 0, weight 0 -> harmless)
    __syncthreads();

    // ---- Phase 4: gather-accumulate (fp16 weights, fp32 accum) ----
    // 4 token groups x 128 lanes. Lane l owns dims {2l,2l+1, 256+2l,256+2l+1,
    // 512+2l,512+2l+1} -> every LDG.32 is a fully-coalesced warp access.
    const int group = tid >> 7;        // 0..3
    const int lane  = tid & 127;       // 0..127
    const __half2* __restrict__ Wt2 = (const __half2*)g_Wt;

    float a0x = 0.f, a0y = 0.f, a1x = 0.f, a1y = 0.f, a2x = 0.f, a2y = 0.f;
#pragma unroll 4
    for (int j = group; j < SEQL; j += 4) {
        float sj = score[j];
        size_t idx = (size_t)tok[j] * ROWH2 + lane;
        __half2 h0 = __ldg(&Wt2[idx +   0]);
        __half2 h1 = __ldg(&Wt2[idx + 128]);
        __half2 h2 = __ldg(&Wt2[idx + 256]);
        float2 f0 = __half22float2(h0);
        float2 f1 = __half22float2(h1);
        float2 f2 = __half22float2(h2);
        a0x = fmaf(sj, f0.x, a0x); a0y = fmaf(sj, f0.y, a0y);
        a1x = fmaf(sj, f1.x, a1x); a1y = fmaf(sj, f1.y, a1y);
        a2x = fmaf(sj, f2.x, a2x); a2y = fmaf(sj, f2.y, a2y);
    }
    atomicAdd(&redbuf[      2 * lane    ], a0x);
    atomicAdd(&redbuf[      2 * lane + 1], a0y);
    atomicAdd(&redbuf[256 + 2 * lane    ], a1x);
    atomicAdd(&redbuf[256 + 2 * lane + 1], a1y);
    atomicAdd(&redbuf[512 + 2 * lane    ], a2x);
    atomicAdd(&redbuf[512 + 2 * lane + 1], a2y);
    __syncthreads();

    // ---- Phase 5: normalize + write ----
    float p = 0.0f;
    for (int d = tid; d < DIM; d += 512) { float v = redbuf[d]; p = fmaf(v, v, p); }
#pragma unroll
    for (int o = 16; o; o >>= 1) p += __shfl_xor_sync(0xFFFFFFFFu, p, o);
    if ((tid & 31) == 0) warpsum[tid >> 5] = p;
    __syncthreads();
    if (tid == 0) {
        float ss = 0.0f;
#pragma unroll
        for (int w = 0; w < 16; w++) ss += warpsum[w];
        warpsum[0] = rsqrtf(fmaxf(ss, 1e-30f));
    }
    __syncthreads();
    float rn = warpsum[0];
    for (int d = tid; d < DIM; d += 512)
        out[(size_t)b * DIM + d] = redbuf[d] * rn;
}

// ---------------------------------------------------------------------------
extern "C" void kernel_launch(void* const* d_in, const int* in_sizes, int n_in,
                              void* d_out, int out_size) {
    const int*   ids  = (const int*)d_in[0];
    const int*   mask = (const int*)d_in[1];
    const float* W    = (const float*)d_in[2];
    float*       out  = (float*)d_out;

    int B = in_sizes[0] / SEQL;

    // W -> Wt (transposed, fp16) into the device-global scratch
    dim3 tg((VOCAB + TP_VT - 1) / TP_VT, DIM / TP_DT);
    transpose_kernel<<<tg, 512>>>(W);

    cudaFuncSetAttribute(bm25_kernel,
                         cudaFuncAttributeMaxDynamicSharedMemorySize, SMEM_BYTES);
    bm25_kernel<<<B, 512, SMEM_BYTES>>>(ids, mask, out);
}

// round 13
// speedup vs baseline: 1.0142x; 1.0142x over previous
#include <cuda_runtime.h>
#include <cuda_fp16.h>

#define VOCAB 30000
#define DIM   768
#define SEQL  512
#define HWORDS (VOCAB / 2)   // packed 16-bit counts, 2 per u32
#define ROWH2 (DIM / 2)      // 384 half2 per Wt row

// Scratch: transposed weights Wt[VOCAB][DIM] (fp16, 46 MB). Device global
// per the allocation rules (no cudaMalloc anywhere).
__device__ __half g_Wt[(size_t)VOCAB * DIM];

// ---------------------------------------------------------------------------
// Transpose W [DIM, VOCAB] (row-major fp32) -> g_Wt [VOCAB, DIM] (fp16).
// (exact R11 version — 24.5us overhead, proven; R12's rework regressed)
// ---------------------------------------------------------------------------
__global__ void transpose_kernel(const float* __restrict__ W) {
    __shared__ float tile[64][33];        // [dim][vocab]
    int t0 = blockIdx.x * 32;             // vocab tile base
    int d0 = blockIdx.y * 64;             // dim tile base
    int x = threadIdx.x;                  // 0..31
    int y = threadIdx.y;                  // 0..7

#pragma unroll
    for (int i = 0; i < 64; i += 8) {
        int d = d0 + y + i;               // < DIM (DIM % 64 == 0)
        int t = t0 + x;
        if (t < VOCAB)
            tile[y + i][x] = W[(size_t)d * VOCAB + t];
    }
    __syncthreads();

    // warp y writes vocab rows t0 + j*8 + y; lane l writes dims (2l, 2l+1)
#pragma unroll
    for (int j = 0; j < 4; j++) {
        int tr = j * 8 + y;               // 0..31 (tile-local vocab row)
        int t  = t0 + tr;
        if (t < VOCAB) {
            __half2 v = __floats2half2_rn(tile[2 * x][tr], tile[2 * x + 1][tr]);
            *(__half2*)&g_Wt[(size_t)t * DIM + d0 + 2 * x] = v;
        }
    }
}

// ---------------------------------------------------------------------------
// Main kernel: one CTA per document row.  (R11 structure + token compaction:
// invalid/duplicate tokens removed before the gather -> ~2.5% fewer L2 bytes.
// Phase-4 loop BODY is byte-identical to R11 — do not restructure it.)
// ---------------------------------------------------------------------------
// smem layout (u32 words): hist[15000] | redbuf[768] | score[512] | tok[512] | warpsum[16] | cnt[1]
#define SMEM_WORDS (HWORDS + DIM + SEQL + SEQL + 16 + 1)
#define SMEM_BYTES (SMEM_WORDS * 4)

__global__ __launch_bounds__(512, 3)
void bm25_kernel(const int* __restrict__ ids,
                 const int* __restrict__ mask,
                 float* __restrict__ out) {
    extern __shared__ unsigned int sm[];
    unsigned int* hist    = sm;                               // HWORDS
    float*        redbuf  = (float*)(sm + HWORDS);            // DIM
    float*        score   = redbuf + DIM;                     // SEQL
    int*          tok     = (int*)(score + SEQL);             // SEQL
    float*        warpsum = (float*)(tok + SEQL);             // 16
    int*          cntp    = (int*)(warpsum + 16);             // 1

    const int tid = threadIdx.x;
    const int b   = blockIdx.x;

    // ---- Phase 1: load token, validity ----
    int id = ids [(size_t)b * SEQL + tid];
    int mk = mask[(size_t)b * SEQL + tid];
    bool valid = (mk == 1) && (id > 100) && (id < VOCAB);
    int  t = valid ? id : 0;

    // zero histogram, reduction buffer, compacted arrays, counter
#pragma unroll
    for (int i = tid; i < HWORDS; i += 512) hist[i] = 0u;
    for (int i = tid; i < DIM;    i += 512) redbuf[i] = 0.0f;
    score[tid] = 0.0f;
    tok[tid]   = 0;
    if (tid == 0) *cntp = 0;

    int doc_len = __syncthreads_count(valid);   // barrier + valid count

    // ---- Phase 2: histogram (tf with multiplicity) ----
    const unsigned sh = ((unsigned)t & 1u) << 4;
    if (valid) atomicAdd(&hist[t >> 1], 1u << sh);
    __syncthreads();

    // ---- Phase 3: dedup + score + compaction ----
    float length_norm = fmaxf(1.0f + 0.75f * ((float)doc_len * 0.01f - 1.0f), 0.5f);
    float s = 0.0f;
    if (valid) {
        unsigned old = atomicAnd(&hist[t >> 1], ~(0xFFFFu << sh));
        unsigned cnt = (old >> sh) & 0xFFFFu;
        if (cnt) {
            float tf = (float)cnt;
            s = tf * 2.2f / (tf + 1.2f * length_norm);   // (K1+1)=2.2, K1=1.2
        }
    }
    if (s > 0.0f) {
        int pos = atomicAdd(cntp, 1);
        score[pos] = s;
        tok[pos]   = t;
    }
    __syncthreads();
    const int n4 = (*cntp + 3) & ~3;   // padded entries are (0, token 0) — harmless

    // ---- Phase 4: gather-accumulate (fp16 weights, fp32 accum) ----
    // 4 token groups x 128 lanes. Lane l owns dims {2l,2l+1, 256+2l,256+2l+1,
    // 512+2l,512+2l+1} -> every LDG.32 is a fully-coalesced warp access.
    const int group = tid >> 7;        // 0..3
    const int lane  = tid & 127;       // 0..127
    const __half2* __restrict__ Wt2 = (const __half2*)g_Wt;

    float a0x = 0.f, a0y = 0.f, a1x = 0.f, a1y = 0.f, a2x = 0.f, a2y = 0.f;
#pragma unroll 4
    for (int j = group; j < n4; j += 4) {
        float sj = score[j];
        size_t idx = (size_t)tok[j] * ROWH2 + lane;
        __half2 h0 = __ldg(&Wt2[idx +   0]);
        __half2 h1 = __ldg(&Wt2[idx + 128]);
        __half2 h2 = __ldg(&Wt2[idx + 256]);
        float2 f0 = __half22float2(h0);
        float2 f1 = __half22float2(h1);
        float2 f2 = __half22float2(h2);
        a0x = fmaf(sj, f0.x, a0x); a0y = fmaf(sj, f0.y, a0y);
        a1x = fmaf(sj, f1.x, a1x); a1y = fmaf(sj, f1.y, a1y);
        a2x = fmaf(sj, f2.x, a2x); a2y = fmaf(sj, f2.y, a2y);
    }
    atomicAdd(&redbuf[      2 * lane    ], a0x);
    atomicAdd(&redbuf[      2 * lane + 1], a0y);
    atomicAdd(&redbuf[256 + 2 * lane    ], a1x);
    atomicAdd(&redbuf[256 + 2 * lane + 1], a1y);
    atomicAdd(&redbuf[512 + 2 * lane    ], a2x);
    atomicAdd(&redbuf[512 + 2 * lane + 1], a2y);
    __syncthreads();

    // ---- Phase 5: normalize + write ----
    float p = 0.0f;
    for (int d = tid; d < DIM; d += 512) { float v = redbuf[d]; p = fmaf(v, v, p); }
#pragma unroll
    for (int o = 16; o; o >>= 1) p += __shfl_xor_sync(0xFFFFFFFFu, p, o);
    if ((tid & 31) == 0) warpsum[tid >> 5] = p;
    __syncthreads();
    if (tid == 0) {
        float ss = 0.0f;
#pragma unroll
        for (int w = 0; w < 16; w++) ss += warpsum[w];
        warpsum[0] = rsqrtf(fmaxf(ss, 1e-30f));
    }
    __syncthreads();
    float rn = warpsum[0];
    for (int d = tid; d < DIM; d += 512)
        out[(size_t)b * DIM + d] = redbuf[d] * rn;
}

// ---------------------------------------------------------------------------
extern "C" void kernel_launch(void* const* d_in, const int* in_sizes, int n_in,
                              void* d_out, int out_size) {
    const int*   ids  = (const int*)d_in[0];
    const int*   mask = (const int*)d_in[1];
    const float* W    = (const float*)d_in[2];
    float*       out  = (float*)d_out;

    int B = in_sizes[0] / SEQL;

    // W -> Wt (transposed, fp16) into the device-global scratch
    dim3 tb(32, 8);
    dim3 tg((VOCAB + 31) / 32, DIM / 64);
    transpose_kernel<<<tg, tb>>>(W);

    cudaFuncSetAttribute(bm25_kernel,
                         cudaFuncAttributeMaxDynamicSharedMemorySize, SMEM_BYTES);
    bm25_kernel<<<B, 512, SMEM_BYTES>>>(ids, mask, out);
}

// round 14
// speedup vs baseline: 1.0272x; 1.0128x over previous
#include <cuda_runtime.h>
#include <cuda_fp16.h>

#define VOCAB 30000
#define DIM   768
#define SEQL  512
#define HWORDS (VOCAB / 2)   // packed 16-bit counts, 2 per u32
#define ROWH2 (DIM / 2)      // 384 half2 per Wt row

// Scratch: transposed weights Wt[VOCAB][DIM] (fp16, 46 MB). Device global
// per the allocation rules (no cudaMalloc anywhere).
__device__ __half g_Wt[(size_t)VOCAB * DIM];

// ---------------------------------------------------------------------------
// Transpose W [DIM, VOCAB] (row-major fp32) -> g_Wt [VOCAB, DIM] (fp16).
// (exact R11 version — proven; R12's rework regressed)
// ---------------------------------------------------------------------------
__global__ void transpose_kernel(const float* __restrict__ W) {
    __shared__ float tile[64][33];        // [dim][vocab]
    int t0 = blockIdx.x * 32;             // vocab tile base
    int d0 = blockIdx.y * 64;             // dim tile base
    int x = threadIdx.x;                  // 0..31
    int y = threadIdx.y;                  // 0..7

#pragma unroll
    for (int i = 0; i < 64; i += 8) {
        int d = d0 + y + i;               // < DIM (DIM % 64 == 0)
        int t = t0 + x;
        if (t < VOCAB)
            tile[y + i][x] = W[(size_t)d * VOCAB + t];
    }
    __syncthreads();

    // warp y writes vocab rows t0 + j*8 + y; lane l writes dims (2l, 2l+1)
#pragma unroll
    for (int j = 0; j < 4; j++) {
        int tr = j * 8 + y;               // 0..31 (tile-local vocab row)
        int t  = t0 + tr;
        if (t < VOCAB) {
            __half2 v = __floats2half2_rn(tile[2 * x][tr], tile[2 * x + 1][tr]);
            *(__half2*)&g_Wt[(size_t)t * DIM + d0 + 2 * x] = v;
        }
    }
}

// ---------------------------------------------------------------------------
// Main kernel: one CTA per document row.  (R11 structure + STATIC-bound token
// compaction: unique tokens packed to a dense prefix, tail padded with
// (score 0, token 0) -> padded iterations gather the single hot row 0.
// Phase-4 loop body AND bound are byte-identical to R11.)
// ---------------------------------------------------------------------------
// smem layout (u32 words): hist[15000] | redbuf[768] | score[512] | tok[512] | warpsum[16] | cnt[1]
#define SMEM_WORDS (HWORDS + DIM + SEQL + SEQL + 16 + 1)
#define SMEM_BYTES (SMEM_WORDS * 4)

__global__ __launch_bounds__(512, 3)
void bm25_kernel(const int* __restrict__ ids,
                 const int* __restrict__ mask,
                 float* __restrict__ out) {
    extern __shared__ unsigned int sm[];
    unsigned int* hist    = sm;                               // HWORDS
    float*        redbuf  = (float*)(sm + HWORDS);            // DIM
    float*        score   = redbuf + DIM;                     // SEQL
    int*          tok     = (int*)(score + SEQL);             // SEQL
    float*        warpsum = (float*)(tok + SEQL);             // 16
    int*          cntp    = (int*)(warpsum + 16);             // 1

    const int tid = threadIdx.x;
    const int b   = blockIdx.x;

    // ---- Phase 1: load token, validity ----
    int id = ids [(size_t)b * SEQL + tid];
    int mk = mask[(size_t)b * SEQL + tid];
    bool valid = (mk == 1) && (id > 100) && (id < VOCAB);
    int  t = valid ? id : 0;

    // zero histogram, reduction buffer, compacted arrays, counter
#pragma unroll
    for (int i = tid; i < HWORDS; i += 512) hist[i] = 0u;
    for (int i = tid; i < DIM;    i += 512) redbuf[i] = 0.0f;
    score[tid] = 0.0f;   // padding default: score 0
    tok[tid]   = 0;      // padding default: token 0 (hot row, ~free)
    if (tid == 0) *cntp = 0;

    int doc_len = __syncthreads_count(valid);   // barrier + valid count

    // ---- Phase 2: histogram (tf with multiplicity) ----
    const unsigned sh = ((unsigned)t & 1u) << 4;
    if (valid) atomicAdd(&hist[t >> 1], 1u << sh);
    __syncthreads();

    // ---- Phase 3: dedup + score + compaction (into dense prefix) ----
    float length_norm = fmaxf(1.0f + 0.75f * ((float)doc_len * 0.01f - 1.0f), 0.5f);
    float s = 0.0f;
    if (valid) {
        unsigned old = atomicAnd(&hist[t >> 1], ~(0xFFFFu << sh));
        unsigned cnt = (old >> sh) & 0xFFFFu;
        if (cnt) {
            float tf = (float)cnt;
            s = tf * 2.2f / (tf + 1.2f * length_norm);   // (K1+1)=2.2, K1=1.2
        }
    }
    if (s > 0.0f) {
        int pos = atomicAdd(cntp, 1);
        score[pos] = s;
        tok[pos]   = t;
    }
    __syncthreads();

    // ---- Phase 4: gather-accumulate (fp16 weights, fp32 accum) ----
    // 4 token groups x 128 lanes. Lane l owns dims {2l,2l+1, 256+2l,256+2l+1,
    // 512+2l,512+2l+1} -> every LDG.32 is a fully-coalesced warp access.
    // Static 512-trip bound (identical to R11); tail iterations hit row 0.
    const int group = tid >> 7;        // 0..3
    const int lane  = tid & 127;       // 0..127
    const __half2* __restrict__ Wt2 = (const __half2*)g_Wt;

    float a0x = 0.f, a0y = 0.f, a1x = 0.f, a1y = 0.f, a2x = 0.f, a2y = 0.f;
#pragma unroll 4
    for (int j = group; j < SEQL; j += 4) {
        float sj = score[j];
        size_t idx = (size_t)tok[j] * ROWH2 + lane;
        __half2 h0 = __ldg(&Wt2[idx +   0]);
        __half2 h1 = __ldg(&Wt2[idx + 128]);
        __half2 h2 = __ldg(&Wt2[idx + 256]);
        float2 f0 = __half22float2(h0);
        float2 f1 = __half22float2(h1);
        float2 f2 = __half22float2(h2);
        a0x = fmaf(sj, f0.x, a0x); a0y = fmaf(sj, f0.y, a0y);
        a1x = fmaf(sj, f1.x, a1x); a1y = fmaf(sj, f1.y, a1y);
        a2x = fmaf(sj, f2.x, a2x); a2y = fmaf(sj, f2.y, a2y);
    }
    atomicAdd(&redbuf[      2 * lane    ], a0x);
    atomicAdd(&redbuf[      2 * lane + 1], a0y);
    atomicAdd(&redbuf[256 + 2 * lane    ], a1x);
    atomicAdd(&redbuf[256 + 2 * lane + 1], a1y);
    atomicAdd(&redbuf[512 + 2 * lane    ], a2x);
    atomicAdd(&redbuf[512 + 2 * lane + 1], a2y);
    __syncthreads();

    // ---- Phase 5: normalize + write ----
    float p = 0.0f;
    for (int d = tid; d < DIM; d += 512) { float v = redbuf[d]; p = fmaf(v, v, p); }
#pragma unroll
    for (int o = 16; o; o >>= 1) p += __shfl_xor_sync(0xFFFFFFFFu, p, o);
    if ((tid & 31) == 0) warpsum[tid >> 5] = p;
    __syncthreads();
    if (tid == 0) {
        float ss = 0.0f;
#pragma unroll
        for (int w = 0; w < 16; w++) ss += warpsum[w];
        warpsum[0] = rsqrtf(fmaxf(ss, 1e-30f));
    }
    __syncthreads();
    float rn = warpsum[0];
    for (int d = tid; d < DIM; d += 512)
        out[(size_t)b * DIM + d] = redbuf[d] * rn;
}

// ---------------------------------------------------------------------------
extern "C" void kernel_launch(void* const* d_in, const int* in_sizes, int n_in,
                              void* d_out, int out_size) {
    const int*   ids  = (const int*)d_in[0];
    const int*   mask = (const int*)d_in[1];
    const float* W    = (const float*)d_in[2];
    float*       out  = (float*)d_out;

    int B = in_sizes[0] / SEQL;

    // W -> Wt (transposed, fp16) into the device-global scratch
    dim3 tb(32, 8);
    dim3 tg((VOCAB + 31) / 32, DIM / 64);
    transpose_kernel<<<tg, tb>>>(W);

    cudaFuncSetAttribute(bm25_kernel,
                         cudaFuncAttributeMaxDynamicSharedMemorySize, SMEM_BYTES);
    bm25_kernel<<<B, 512, SMEM_BYTES>>>(ids, mask, out);
}